// round 3
// baseline (speedup 1.0000x reference)
#include <cuda_runtime.h>
#include <math.h>

#define B     4
#define T     16
#define HID   64
#define HW    64
#define PLANE 4096   // 64*64

// Inter-layer sequence buffers + cell-state scratch (allocation-free rule:
// __device__ globals). 67 MB + 67 MB + 4 MB.
__device__ float g_buf0[(size_t)B * T * HID * PLANE];
__device__ float g_buf1[(size_t)B * T * HID * PLANE];
__device__ float g_c[(size_t)B * HID * PLANE];

__device__ __forceinline__ float sigm(float v) { return 1.f / (1.f + expf(-v)); }

// One fused step: gates = conv3x3_dil([xt; h_{t-1}]) + b ; LSTM update ; residual.
// h_{t-1} is read from the output sequence at t-1 (carry == stored output).
// Block: 2 hid channels x 256 pixels (4 rows x 64 cols). Thread: 1 hid ch x 4 px.
template <int LAYER, int CIN_X, int DIL>
__global__ void __launch_bounds__(128) lstm_step(
    const float* __restrict__ x_in,   // x_seq (used by layer 0 only)
    const float* __restrict__ gw,     // [4*HID][CIN_X+HID][3][3]
    const float* __restrict__ gb,     // [4*HID]
    const float* __restrict__ rw,     // [HID][CIN_X] (layer 0) or null
    const float* __restrict__ rb,     // [HID] or null
    float* __restrict__ out_final,    // d_out (written by layer 2)
    int t)
{
    constexpr int CC = CIN_X + HID;   // concat channels
    constexpr int W9 = CC * 9;

    __shared__ float ws[2][4][W9];    // [co_local][gate][ci*9+k]
    __shared__ float rws[2][CIN_X];   // layer-0 residual 1x1 weights

    const int tid      = threadIdx.x;         // 0..127
    const int ytile    = blockIdx.x;          // 0..15 (4 rows each)
    const int co_group = blockIdx.y;          // 0..31 (2 hid ch each)
    const int b        = blockIdx.z;          // 0..3
    const int co_local = tid >> 6;            // 0..1
    const int s        = tid & 63;
    const int row      = ytile * 4 + (s >> 4);
    const int x0       = (s & 15) << 2;       // 4 px per thread
    const int co       = co_group * 2 + co_local;

    // Cooperative weight stage (warp-uniform broadcast reads later).
    for (int i = tid; i < 8 * W9; i += 128) {
        int cl = i / (4 * W9);
        int r  = i - cl * 4 * W9;
        int gi = r / W9;
        int k  = r - gi * W9;
        ws[cl][gi][k] = gw[(size_t)(gi * HID + co_group * 2 + cl) * W9 + k];
    }
    if (LAYER == 0 && tid < 2 * CIN_X) {
        rws[tid / CIN_X][tid % CIN_X] =
            rw[(co_group * 2 + tid / CIN_X) * CIN_X + (tid % CIN_X)];
    }
    __syncthreads();

    const float* seq_in  = (LAYER == 0) ? x_in : ((LAYER == 1) ? g_buf0 : g_buf1);
    float*       seq_out = (LAYER == 0) ? g_buf0 : ((LAYER == 1) ? g_buf1 : out_final);

    const float* xt = seq_in + (size_t)(b * T + t) * CIN_X * PLANE;
    const float* hp = seq_out + (size_t)(b * T + (t - 1)) * HID * PLANE; // only valid t>0
    const int ctot  = (t > 0) ? CC : CIN_X;   // h==0 at t=0: skip h channels entirely

    float acc[4][4] = {};                     // [gate][px]

    for (int ci = 0; ci < ctot; ci++) {
        const float* plane = (ci < CIN_X) ? (xt + (size_t)ci * PLANE)
                                          : (hp + (size_t)(ci - CIN_X) * PLANE);
#pragma unroll
        for (int ky = 0; ky < 3; ky++) {
            const int yy = row + (ky - 1) * DIL;
            if (yy < 0 || yy >= HW) continue;  // zero padding
            const float* rp = plane + yy * HW;
            float vals[4 + 2 * DIL];
#pragma unroll
            for (int j = 0; j < 4 + 2 * DIL; j++) {
                int xx = x0 - DIL + j;
                vals[j] = (xx >= 0 && xx < HW) ? __ldg(rp + xx) : 0.f;
            }
#pragma unroll
            for (int kx = 0; kx < 3; kx++) {
#pragma unroll
                for (int g = 0; g < 4; g++) {
                    const float w = ws[co_local][g][ci * 9 + ky * 3 + kx];
#pragma unroll
                    for (int px = 0; px < 4; px++)
                        acc[g][px] = fmaf(w, vals[px + kx * DIL], acc[g][px]);
                }
            }
        }
    }

    // Bias
    float gbv[4];
#pragma unroll
    for (int g = 0; g < 4; g++) gbv[g] = __ldg(gb + g * HID + co);

    // Residual
    float res[4];
    if (LAYER == 0) {
        float rbv = __ldg(rb + co);
#pragma unroll
        for (int px = 0; px < 4; px++) res[px] = rbv;
        for (int ci = 0; ci < CIN_X; ci++) {
            float w        = rws[co_local][ci];
            const float* p = xt + (size_t)ci * PLANE + row * HW + x0;
#pragma unroll
            for (int px = 0; px < 4; px++) res[px] = fmaf(w, __ldg(p + px), res[px]);
        }
    } else {
        const float* p = xt + (size_t)co * PLANE + row * HW + x0;
#pragma unroll
        for (int px = 0; px < 4; px++) res[px] = __ldg(p + px);
    }

    float* cptr = g_c + (size_t)(b * HID + co) * PLANE + row * HW + x0;
    float* optr = seq_out + ((size_t)(b * T + t) * HID + co) * PLANE + row * HW + x0;

#pragma unroll
    for (int px = 0; px < 4; px++) {
        float iv    = sigm(acc[0][px] + gbv[0]);
        float fv    = sigm(acc[1][px] + gbv[1]);
        float gv    = tanhf(acc[2][px] + gbv[2]);
        float ov    = sigm(acc[3][px] + gbv[3]);
        float c_old = (t > 0) ? cptr[px] : 0.f;
        float c_new = fv * c_old + iv * gv;
        float h_new = ov * tanhf(c_new);
        cptr[px] = c_new;
        optr[px] = h_new + res[px];
    }
}

extern "C" void kernel_launch(void* const* d_in, const int* in_sizes, int n_in,
                              void* d_out, int out_size)
{
    (void)in_sizes; (void)n_in; (void)out_size;
    const float* x   = (const float*)d_in[0];
    const float* gw0 = (const float*)d_in[1];
    const float* gb0 = (const float*)d_in[2];
    const float* gw1 = (const float*)d_in[3];
    const float* gb1 = (const float*)d_in[4];
    const float* gw2 = (const float*)d_in[5];
    const float* gb2 = (const float*)d_in[6];
    const float* rw0 = (const float*)d_in[7];
    const float* rb0 = (const float*)d_in[8];
    float* out = (float*)d_out;

    dim3 grid(16, 32, B);   // y-tiles x co-groups x batch
    for (int t = 0; t < T; t++)
        lstm_step<0, 32, 1><<<grid, 128>>>(x, gw0, gb0, rw0, rb0, out, t);
    for (int t = 0; t < T; t++)
        lstm_step<1, 64, 2><<<grid, 128>>>(x, gw1, gb1, nullptr, nullptr, out, t);
    for (int t = 0; t < T; t++)
        lstm_step<2, 64, 4><<<grid, 128>>>(x, gw2, gb2, nullptr, nullptr, out, t);
}

// round 4
// speedup vs baseline: 1.0013x; 1.0013x over previous
#include <cuda_runtime.h>
#include <math.h>

#define B     4
#define T     16
#define HID   64
#define HW    64
#define PLANE 4096   // 64*64

// Inter-layer sequence buffers + cell-state scratch (allocation-free rule:
// __device__ globals). 67 MB + 67 MB + 4 MB.
__device__ float g_buf0[(size_t)B * T * HID * PLANE];
__device__ float g_buf1[(size_t)B * T * HID * PLANE];
__device__ float g_c[(size_t)B * HID * PLANE];

__device__ __forceinline__ float sigm(float v) { return 1.f / (1.f + expf(-v)); }

// One fused step: gates = conv3x3_dil([xt; h_{t-1}]) + b ; LSTM update ; residual.
// h_{t-1} is read from the output sequence at t-1 (carry == stored output).
// Block: 2 hid channels x 256 pixels (4 rows x 64 cols). Thread: 1 hid ch x 4 px.
template <int LAYER, int CIN_X, int DIL>
__global__ void __launch_bounds__(128) lstm_step(
    const float* __restrict__ x_in,   // x_seq (used by layer 0 only)
    const float* __restrict__ gw,     // [4*HID][CIN_X+HID][3][3]
    const float* __restrict__ gb,     // [4*HID]
    const float* __restrict__ rw,     // [HID][CIN_X] (layer 0) or null
    const float* __restrict__ rb,     // [HID] or null
    float* __restrict__ out_final,    // d_out (written by layer 2)
    int t)
{
    constexpr int CC = CIN_X + HID;   // concat channels
    constexpr int W9 = CC * 9;

    __shared__ float ws[2][4][W9];    // [co_local][gate][ci*9+k]
    __shared__ float rws[2][CIN_X];   // layer-0 residual 1x1 weights

    const int tid      = threadIdx.x;         // 0..127
    const int ytile    = blockIdx.x;          // 0..15 (4 rows each)
    const int co_group = blockIdx.y;          // 0..31 (2 hid ch each)
    const int b        = blockIdx.z;          // 0..3
    const int co_local = tid >> 6;            // 0..1
    const int s        = tid & 63;
    const int row      = ytile * 4 + (s >> 4);
    const int x0       = (s & 15) << 2;       // 4 px per thread
    const int co       = co_group * 2 + co_local;

    // Cooperative weight stage (warp-uniform broadcast reads later).
    for (int i = tid; i < 8 * W9; i += 128) {
        int cl = i / (4 * W9);
        int r  = i - cl * 4 * W9;
        int gi = r / W9;
        int k  = r - gi * W9;
        ws[cl][gi][k] = gw[(size_t)(gi * HID + co_group * 2 + cl) * W9 + k];
    }
    if (LAYER == 0 && tid < 2 * CIN_X) {
        rws[tid / CIN_X][tid % CIN_X] =
            rw[(co_group * 2 + tid / CIN_X) * CIN_X + (tid % CIN_X)];
    }
    __syncthreads();

    const float* seq_in  = (LAYER == 0) ? x_in : ((LAYER == 1) ? g_buf0 : g_buf1);
    float*       seq_out = (LAYER == 0) ? g_buf0 : ((LAYER == 1) ? g_buf1 : out_final);

    const float* xt = seq_in + (size_t)(b * T + t) * CIN_X * PLANE;
    const float* hp = seq_out + (size_t)(b * T + (t - 1)) * HID * PLANE; // only valid t>0
    const int ctot  = (t > 0) ? CC : CIN_X;   // h==0 at t=0: skip h channels entirely

    float acc[4][4] = {};                     // [gate][px]

    for (int ci = 0; ci < ctot; ci++) {
        const float* plane = (ci < CIN_X) ? (xt + (size_t)ci * PLANE)
                                          : (hp + (size_t)(ci - CIN_X) * PLANE);
#pragma unroll
        for (int ky = 0; ky < 3; ky++) {
            const int yy = row + (ky - 1) * DIL;
            if (yy < 0 || yy >= HW) continue;  // zero padding
            const float* rp = plane + yy * HW;
            float vals[4 + 2 * DIL];
#pragma unroll
            for (int j = 0; j < 4 + 2 * DIL; j++) {
                int xx = x0 - DIL + j;
                vals[j] = (xx >= 0 && xx < HW) ? __ldg(rp + xx) : 0.f;
            }
#pragma unroll
            for (int kx = 0; kx < 3; kx++) {
#pragma unroll
                for (int g = 0; g < 4; g++) {
                    const float w = ws[co_local][g][ci * 9 + ky * 3 + kx];
#pragma unroll
                    for (int px = 0; px < 4; px++)
                        acc[g][px] = fmaf(w, vals[px + kx * DIL], acc[g][px]);
                }
            }
        }
    }

    // Bias
    float gbv[4];
#pragma unroll
    for (int g = 0; g < 4; g++) gbv[g] = __ldg(gb + g * HID + co);

    // Residual
    float res[4];
    if (LAYER == 0) {
        float rbv = __ldg(rb + co);
#pragma unroll
        for (int px = 0; px < 4; px++) res[px] = rbv;
        for (int ci = 0; ci < CIN_X; ci++) {
            float w        = rws[co_local][ci];
            const float* p = xt + (size_t)ci * PLANE + row * HW + x0;
#pragma unroll
            for (int px = 0; px < 4; px++) res[px] = fmaf(w, __ldg(p + px), res[px]);
        }
    } else {
        const float* p = xt + (size_t)co * PLANE + row * HW + x0;
#pragma unroll
        for (int px = 0; px < 4; px++) res[px] = __ldg(p + px);
    }

    float* cptr = g_c + (size_t)(b * HID + co) * PLANE + row * HW + x0;
    float* optr = seq_out + ((size_t)(b * T + t) * HID + co) * PLANE + row * HW + x0;

#pragma unroll
    for (int px = 0; px < 4; px++) {
        float iv    = sigm(acc[0][px] + gbv[0]);
        float fv    = sigm(acc[1][px] + gbv[1]);
        float gv    = tanhf(acc[2][px] + gbv[2]);
        float ov    = sigm(acc[3][px] + gbv[3]);
        float c_old = (t > 0) ? cptr[px] : 0.f;
        float c_new = fv * c_old + iv * gv;
        float h_new = ov * tanhf(c_new);
        cptr[px] = c_new;
        optr[px] = h_new + res[px];
    }
}

extern "C" void kernel_launch(void* const* d_in, const int* in_sizes, int n_in,
                              void* d_out, int out_size)
{
    (void)in_sizes; (void)n_in; (void)out_size;
    const float* x   = (const float*)d_in[0];
    const float* gw0 = (const float*)d_in[1];
    const float* gb0 = (const float*)d_in[2];
    const float* gw1 = (const float*)d_in[3];
    const float* gb1 = (const float*)d_in[4];
    const float* gw2 = (const float*)d_in[5];
    const float* gb2 = (const float*)d_in[6];
    const float* rw0 = (const float*)d_in[7];
    const float* rb0 = (const float*)d_in[8];
    float* out = (float*)d_out;

    dim3 grid(16, 32, B);   // y-tiles x co-groups x batch
    for (int t = 0; t < T; t++)
        lstm_step<0, 32, 1><<<grid, 128>>>(x, gw0, gb0, rw0, rb0, out, t);
    for (int t = 0; t < T; t++)
        lstm_step<1, 64, 2><<<grid, 128>>>(x, gw1, gb1, nullptr, nullptr, out, t);
    for (int t = 0; t < T; t++)
        lstm_step<2, 64, 4><<<grid, 128>>>(x, gw2, gb2, nullptr, nullptr, out, t);
}

// round 5
// speedup vs baseline: 1.6237x; 1.6216x over previous
#include <cuda_runtime.h>
#include <math.h>

#define B     4
#define T     16
#define HID   64
#define HW    64
#define PLANE 4096   // 64*64

__device__ float g_buf0[(size_t)B * T * HID * PLANE];
__device__ float g_buf1[(size_t)B * T * HID * PLANE];
__device__ float g_c[(size_t)B * HID * PLANE];

__device__ __forceinline__ float sigm(float v) { return 1.f / (1.f + expf(-v)); }

// Accumulate one input plane's 3x3 (dilated) contribution for 4 gates x 4 px.
// wci: float4-per-(ky,kx), components = 4 gates. 3 LDS.128 + <=3 vector LDG per ky.
template <int DIL>
__device__ __forceinline__ void accum_plane(
    const float* __restrict__ plane, const float4* __restrict__ wci,
    int row, int x0, float acc[4][4])
{
#pragma unroll
    for (int ky = 0; ky < 3; ky++) {
        const int yy = row + (ky - 1) * DIL;
        if (yy < 0 || yy >= HW) continue;
        const float* rp = plane + yy * HW;

        float vals[4 + 2 * DIL];
        {
            float4 m = __ldg((const float4*)(rp + x0));
            vals[DIL + 0] = m.x; vals[DIL + 1] = m.y;
            vals[DIL + 2] = m.z; vals[DIL + 3] = m.w;
        }
        if (DIL == 1) {
            vals[0] = (x0 > 0)      ? __ldg(rp + x0 - 1) : 0.f;
            vals[5] = (x0 + 4 < HW) ? __ldg(rp + x0 + 4) : 0.f;
        } else if (DIL == 2) {
            if (x0 > 0) {
                float2 l = __ldg((const float2*)(rp + x0 - 2));
                vals[0] = l.x; vals[1] = l.y;
            } else { vals[0] = 0.f; vals[1] = 0.f; }
            if (x0 + 4 < HW) {
                float2 r = __ldg((const float2*)(rp + x0 + 4));
                vals[6] = r.x; vals[7] = r.y;
            } else { vals[6] = 0.f; vals[7] = 0.f; }
        } else {  // DIL == 4
            if (x0 > 0) {
                float4 l = __ldg((const float4*)(rp + x0 - 4));
                vals[0] = l.x; vals[1] = l.y; vals[2] = l.z; vals[3] = l.w;
            } else { vals[0] = vals[1] = vals[2] = vals[3] = 0.f; }
            if (x0 + 4 < HW) {
                float4 r = __ldg((const float4*)(rp + x0 + 4));
                vals[8] = r.x; vals[9] = r.y; vals[10] = r.z; vals[11] = r.w;
            } else { vals[8] = vals[9] = vals[10] = vals[11] = 0.f; }
        }

#pragma unroll
        for (int kx = 0; kx < 3; kx++) {
            const float4 w4 = wci[ky * 3 + kx];   // LDS.128 broadcast: 4 gates
#pragma unroll
            for (int px = 0; px < 4; px++) {
                const float v = vals[px + kx * DIL];
                acc[0][px] = fmaf(w4.x, v, acc[0][px]);
                acc[1][px] = fmaf(w4.y, v, acc[1][px]);
                acc[2][px] = fmaf(w4.z, v, acc[2][px]);
                acc[3][px] = fmaf(w4.w, v, acc[3][px]);
            }
        }
    }
}

// One fused step. Block: 2 hid ch x 256 px (4 rows x 64 cols). Thread: 1 ch x 4 px.
template <int LAYER, int CIN_X, int DIL>
__global__ void __launch_bounds__(128) lstm_step(
    const float* __restrict__ x_in,
    const float* __restrict__ gw,     // [4*HID][CC][3][3]
    const float* __restrict__ gb,     // [4*HID]
    const float* __restrict__ rw,     // [HID][CIN_X] (layer 0) or null
    const float* __restrict__ rb,
    float* __restrict__ out_final,
    int t)
{
    constexpr int CC = CIN_X + HID;

    __shared__ float4 ws4[2][CC * 9];   // [co_local][ci*9 + ky*3 + kx] -> 4 gates
    __shared__ float  rws[2][CIN_X];

    const int tid      = threadIdx.x;
    const int ytile    = blockIdx.x;          // 16 tiles of 4 rows
    const int co_group = blockIdx.y;          // 32 groups of 2 ch
    const int b        = blockIdx.z;
    const int co_local = tid >> 6;
    const int s        = tid & 63;
    const int row      = ytile * 4 + (s >> 4);
    const int x0       = (s & 15) << 2;
    const int co       = co_group * 2 + co_local;

    // Stage gate weights, gate-vectorized: smem[((cl*CC+ci)*9+k)*4 + g].
    {
        float* wsf = (float*)ws4;
        for (int i = tid; i < 2 * CC * 9 * 4; i += 128) {
            int g  = i & 3;
            int r  = i >> 2;                 // (cl*CC + ci)*9 + k
            int cl = r / (CC * 9);
            int ck = r - cl * CC * 9;        // ci*9 + k
            wsf[i] = gw[(size_t)(g * HID + co_group * 2 + cl) * (CC * 9) + ck];
        }
    }
    if (LAYER == 0 && tid < 2 * CIN_X)
        rws[tid / CIN_X][tid % CIN_X] =
            rw[(co_group * 2 + tid / CIN_X) * CIN_X + (tid % CIN_X)];
    __syncthreads();

    const float* seq_in  = (LAYER == 0) ? x_in : ((LAYER == 1) ? g_buf0 : g_buf1);
    float*       seq_out = (LAYER == 0) ? g_buf0 : ((LAYER == 1) ? g_buf1 : out_final);

    const float* xt = seq_in + (size_t)(b * T + t) * CIN_X * PLANE;
    const float* hp = seq_out + (size_t)(b * T + (t - 1)) * HID * PLANE;  // valid t>0

    float acc[4][4] = {};
    const float4* wbase = ws4[co_local];

    for (int ci = 0; ci < CIN_X; ci++)
        accum_plane<DIL>(xt + (size_t)ci * PLANE, wbase + ci * 9, row, x0, acc);
    if (t > 0) {
        for (int ci = 0; ci < HID; ci++)
            accum_plane<DIL>(hp + (size_t)ci * PLANE, wbase + (CIN_X + ci) * 9,
                             row, x0, acc);
    }

    float gbv[4];
#pragma unroll
    for (int g = 0; g < 4; g++) gbv[g] = __ldg(gb + g * HID + co);

    // Residual
    float res[4];
    if (LAYER == 0) {
        float rbv = __ldg(rb + co);
#pragma unroll
        for (int px = 0; px < 4; px++) res[px] = rbv;
        for (int ci = 0; ci < CIN_X; ci++) {
            float w  = rws[co_local][ci];
            float4 p = __ldg((const float4*)(xt + (size_t)ci * PLANE + row * HW + x0));
            res[0] = fmaf(w, p.x, res[0]);
            res[1] = fmaf(w, p.y, res[1]);
            res[2] = fmaf(w, p.z, res[2]);
            res[3] = fmaf(w, p.w, res[3]);
        }
    } else {
        float4 p = __ldg((const float4*)(xt + (size_t)co * PLANE + row * HW + x0));
        res[0] = p.x; res[1] = p.y; res[2] = p.z; res[3] = p.w;
    }

    float* cptr = g_c + (size_t)(b * HID + co) * PLANE + row * HW + x0;
    float* optr = seq_out + ((size_t)(b * T + t) * HID + co) * PLANE + row * HW + x0;

    float4 c_old = (t > 0) ? *(const float4*)cptr : make_float4(0.f, 0.f, 0.f, 0.f);
    float co_a[4] = {c_old.x, c_old.y, c_old.z, c_old.w};
    float cn_a[4], ho_a[4];
#pragma unroll
    for (int px = 0; px < 4; px++) {
        float iv = sigm(acc[0][px] + gbv[0]);
        float fv = sigm(acc[1][px] + gbv[1]);
        float gv = tanhf(acc[2][px] + gbv[2]);
        float ov = sigm(acc[3][px] + gbv[3]);
        float cn = fv * co_a[px] + iv * gv;
        cn_a[px] = cn;
        ho_a[px] = ov * tanhf(cn) + res[px];
    }
    *(float4*)cptr = make_float4(cn_a[0], cn_a[1], cn_a[2], cn_a[3]);
    *(float4*)optr = make_float4(ho_a[0], ho_a[1], ho_a[2], ho_a[3]);
}

extern "C" void kernel_launch(void* const* d_in, const int* in_sizes, int n_in,
                              void* d_out, int out_size)
{
    (void)in_sizes; (void)n_in; (void)out_size;
    const float* x   = (const float*)d_in[0];
    const float* gw0 = (const float*)d_in[1];
    const float* gb0 = (const float*)d_in[2];
    const float* gw1 = (const float*)d_in[3];
    const float* gb1 = (const float*)d_in[4];
    const float* gw2 = (const float*)d_in[5];
    const float* gb2 = (const float*)d_in[6];
    const float* rw0 = (const float*)d_in[7];
    const float* rb0 = (const float*)d_in[8];
    float* out = (float*)d_out;

    dim3 grid(16, 32, B);
    for (int t = 0; t < T; t++)
        lstm_step<0, 32, 1><<<grid, 128>>>(x, gw0, gb0, rw0, rb0, out, t);
    for (int t = 0; t < T; t++)
        lstm_step<1, 64, 2><<<grid, 128>>>(x, gw1, gb1, nullptr, nullptr, out, t);
    for (int t = 0; t < T; t++)
        lstm_step<2, 64, 4><<<grid, 128>>>(x, gw2, gb2, nullptr, nullptr, out, t);
}

// round 6
// speedup vs baseline: 1.7428x; 1.0733x over previous
#include <cuda_runtime.h>
#include <math.h>

#define B     4
#define T     16
#define HID   64
#define HW    64
#define PLANE 4096   // 64*64

__device__ float g_buf0[(size_t)B * T * HID * PLANE];
__device__ float g_buf1[(size_t)B * T * HID * PLANE];
__device__ float g_c[(size_t)B * HID * PLANE];

__device__ __forceinline__ float tanh_fast(float x) {
    float y;
    asm("tanh.approx.f32 %0, %1;" : "=f"(y) : "f"(x));
    return y;
}
__device__ __forceinline__ float sigm(float v) {
    return fmaf(tanh_fast(0.5f * v), 0.5f, 0.5f);
}

// Accumulate one plane's dilated 3x3 contribution: 4 gates x 8 px per thread.
// Per ky: <=4 vector LDG + 3 LDS.128 against 96 FFMAs.
template <int DIL>
__device__ __forceinline__ void accum_plane(
    const float* __restrict__ plane, const float4* __restrict__ wci,
    int row, int x0, float acc[4][8])
{
#pragma unroll
    for (int ky = 0; ky < 3; ky++) {
        const int yy = row + (ky - 1) * DIL;
        if (yy < 0 || yy >= HW) continue;
        const float* rp = plane + yy * HW;

        float vals[8 + 2 * DIL];
        {
            float4 m0 = __ldg((const float4*)(rp + x0));
            float4 m1 = __ldg((const float4*)(rp + x0 + 4));
            vals[DIL + 0] = m0.x; vals[DIL + 1] = m0.y;
            vals[DIL + 2] = m0.z; vals[DIL + 3] = m0.w;
            vals[DIL + 4] = m1.x; vals[DIL + 5] = m1.y;
            vals[DIL + 6] = m1.z; vals[DIL + 7] = m1.w;
        }
        if (DIL == 1) {
            vals[0] = (x0 > 0)      ? __ldg(rp + x0 - 1) : 0.f;
            vals[9] = (x0 + 8 < HW) ? __ldg(rp + x0 + 8) : 0.f;
        } else if (DIL == 2) {
            if (x0 > 0) {
                float2 l = __ldg((const float2*)(rp + x0 - 2));
                vals[0] = l.x; vals[1] = l.y;
            } else { vals[0] = 0.f; vals[1] = 0.f; }
            if (x0 + 8 < HW) {
                float2 r = __ldg((const float2*)(rp + x0 + 8));
                vals[10] = r.x; vals[11] = r.y;
            } else { vals[10] = 0.f; vals[11] = 0.f; }
        } else {  // DIL == 4
            if (x0 > 0) {
                float4 l = __ldg((const float4*)(rp + x0 - 4));
                vals[0] = l.x; vals[1] = l.y; vals[2] = l.z; vals[3] = l.w;
            } else { vals[0] = vals[1] = vals[2] = vals[3] = 0.f; }
            if (x0 + 8 < HW) {
                float4 r = __ldg((const float4*)(rp + x0 + 8));
                vals[12] = r.x; vals[13] = r.y; vals[14] = r.z; vals[15] = r.w;
            } else { vals[12] = vals[13] = vals[14] = vals[15] = 0.f; }
        }

#pragma unroll
        for (int kx = 0; kx < 3; kx++) {
            const float4 w4 = wci[ky * 3 + kx];   // LDS.128 broadcast (4 gates)
#pragma unroll
            for (int px = 0; px < 8; px++) {
                const float v = vals[px + kx * DIL];
                acc[0][px] = fmaf(w4.x, v, acc[0][px]);
                acc[1][px] = fmaf(w4.y, v, acc[1][px]);
                acc[2][px] = fmaf(w4.z, v, acc[2][px]);
                acc[3][px] = fmaf(w4.w, v, acc[3][px]);
            }
        }
    }
}

// One fused step. Block: 2 hid ch x (8 rows x 64 cols). Thread: 1 ch x 8 px.
template <int LAYER, int CIN_X, int DIL>
__global__ void __launch_bounds__(128) lstm_step(
    const float* __restrict__ x_in,
    const float* __restrict__ gw,     // [4*HID][CC][3][3]
    const float* __restrict__ gb,     // [4*HID]
    const float* __restrict__ rw,     // [HID][CIN_X] (layer 0) or null
    const float* __restrict__ rb,
    float* __restrict__ out_final,
    int t)
{
    constexpr int CC = CIN_X + HID;

    __shared__ float4 ws4[2][CC * 9];   // [co_local][ci*9+k] -> 4 gates
    __shared__ float  rws[2][CIN_X];

    const int tid      = threadIdx.x;
    const int ytile    = blockIdx.x;          // 8 tiles of 8 rows
    const int co_group = blockIdx.y;          // 32 groups of 2 ch
    const int b        = blockIdx.z;
    const int co_local = tid >> 6;
    const int s        = tid & 63;
    const int row      = ytile * 8 + (s >> 3);
    const int x0       = (s & 7) << 3;        // 8 px per thread
    const int co       = co_group * 2 + co_local;

    {
        float* wsf = (float*)ws4;
        for (int i = tid; i < 2 * CC * 9 * 4; i += 128) {
            int g  = i & 3;
            int r  = i >> 2;
            int cl = r / (CC * 9);
            int ck = r - cl * CC * 9;
            wsf[i] = gw[(size_t)(g * HID + co_group * 2 + cl) * (CC * 9) + ck];
        }
    }
    if (LAYER == 0 && tid < 2 * CIN_X)
        rws[tid / CIN_X][tid % CIN_X] =
            rw[(co_group * 2 + tid / CIN_X) * CIN_X + (tid % CIN_X)];
    __syncthreads();

    const float* seq_in  = (LAYER == 0) ? x_in : ((LAYER == 1) ? g_buf0 : g_buf1);
    float*       seq_out = (LAYER == 0) ? g_buf0 : ((LAYER == 1) ? g_buf1 : out_final);

    const float* xt = seq_in + (size_t)(b * T + t) * CIN_X * PLANE;
    const float* hp = seq_out + (size_t)(b * T + (t - 1)) * HID * PLANE;  // valid t>0

    float acc[4][8] = {};
    const float4* wbase = ws4[co_local];

    {
        const float* plane = xt;
        const float4* wp = wbase;
        for (int ci = 0; ci < CIN_X; ci++, plane += PLANE, wp += 9)
            accum_plane<DIL>(plane, wp, row, x0, acc);
    }
    if (t > 0) {
        const float* plane = hp;
        const float4* wp = wbase + CIN_X * 9;
        for (int ci = 0; ci < HID; ci++, plane += PLANE, wp += 9)
            accum_plane<DIL>(plane, wp, row, x0, acc);
    }

    float gbv[4];
#pragma unroll
    for (int g = 0; g < 4; g++) gbv[g] = __ldg(gb + g * HID + co);

    // Residual
    float res[8];
    if (LAYER == 0) {
        float rbv = __ldg(rb + co);
#pragma unroll
        for (int px = 0; px < 8; px++) res[px] = rbv;
        const float* p = xt + row * HW + x0;
        for (int ci = 0; ci < CIN_X; ci++, p += PLANE) {
            float w   = rws[co_local][ci];
            float4 p0 = __ldg((const float4*)p);
            float4 p1 = __ldg((const float4*)(p + 4));
            res[0] = fmaf(w, p0.x, res[0]); res[1] = fmaf(w, p0.y, res[1]);
            res[2] = fmaf(w, p0.z, res[2]); res[3] = fmaf(w, p0.w, res[3]);
            res[4] = fmaf(w, p1.x, res[4]); res[5] = fmaf(w, p1.y, res[5]);
            res[6] = fmaf(w, p1.z, res[6]); res[7] = fmaf(w, p1.w, res[7]);
        }
    } else {
        const float* p = xt + (size_t)co * PLANE + row * HW + x0;
        float4 p0 = __ldg((const float4*)p);
        float4 p1 = __ldg((const float4*)(p + 4));
        res[0] = p0.x; res[1] = p0.y; res[2] = p0.z; res[3] = p0.w;
        res[4] = p1.x; res[5] = p1.y; res[6] = p1.z; res[7] = p1.w;
    }

    float* cptr = g_c + (size_t)(b * HID + co) * PLANE + row * HW + x0;
    float* optr = seq_out + ((size_t)(b * T + t) * HID + co) * PLANE + row * HW + x0;

    float co_a[8];
    if (t > 0) {
        float4 c0 = *(const float4*)cptr;
        float4 c1 = *(const float4*)(cptr + 4);
        co_a[0] = c0.x; co_a[1] = c0.y; co_a[2] = c0.z; co_a[3] = c0.w;
        co_a[4] = c1.x; co_a[5] = c1.y; co_a[6] = c1.z; co_a[7] = c1.w;
    } else {
#pragma unroll
        for (int px = 0; px < 8; px++) co_a[px] = 0.f;
    }

    float cn_a[8], ho_a[8];
#pragma unroll
    for (int px = 0; px < 8; px++) {
        float iv = sigm(acc[0][px] + gbv[0]);
        float fv = sigm(acc[1][px] + gbv[1]);
        float gv = tanh_fast(acc[2][px] + gbv[2]);
        float ov = sigm(acc[3][px] + gbv[3]);
        float cn = fv * co_a[px] + iv * gv;
        cn_a[px] = cn;
        ho_a[px] = ov * tanh_fast(cn) + res[px];
    }
    *(float4*)cptr       = make_float4(cn_a[0], cn_a[1], cn_a[2], cn_a[3]);
    *(float4*)(cptr + 4) = make_float4(cn_a[4], cn_a[5], cn_a[6], cn_a[7]);
    *(float4*)optr       = make_float4(ho_a[0], ho_a[1], ho_a[2], ho_a[3]);
    *(float4*)(optr + 4) = make_float4(ho_a[4], ho_a[5], ho_a[6], ho_a[7]);
}

extern "C" void kernel_launch(void* const* d_in, const int* in_sizes, int n_in,
                              void* d_out, int out_size)
{
    (void)in_sizes; (void)n_in; (void)out_size;
    const float* x   = (const float*)d_in[0];
    const float* gw0 = (const float*)d_in[1];
    const float* gb0 = (const float*)d_in[2];
    const float* gw1 = (const float*)d_in[3];
    const float* gb1 = (const float*)d_in[4];
    const float* gw2 = (const float*)d_in[5];
    const float* gb2 = (const float*)d_in[6];
    const float* rw0 = (const float*)d_in[7];
    const float* rb0 = (const float*)d_in[8];
    float* out = (float*)d_out;

    dim3 grid(8, 32, B);   // 8 row-tiles x 32 ch-groups x batch
    for (int t = 0; t < T; t++)
        lstm_step<0, 32, 1><<<grid, 128>>>(x, gw0, gb0, rw0, rb0, out, t);
    for (int t = 0; t < T; t++)
        lstm_step<1, 64, 2><<<grid, 128>>>(x, gw1, gb1, nullptr, nullptr, out, t);
    for (int t = 0; t < T; t++)
        lstm_step<2, 64, 4><<<grid, 128>>>(x, gw2, gb2, nullptr, nullptr, out, t);
}

// round 7
// speedup vs baseline: 2.2599x; 1.2967x over previous
#include <cuda_runtime.h>
#include <math.h>

#define B     4
#define T     16
#define HID   64
#define HW    64
#define PLANE 4096   // 64*64

__device__ float g_buf0[(size_t)B * T * HID * PLANE];
__device__ float g_buf1[(size_t)B * T * HID * PLANE];
__device__ float g_c[(size_t)B * HID * PLANE];

__device__ __forceinline__ float tanh_fast(float x) {
    float y;
    asm("tanh.approx.f32 %0, %1;" : "=f"(y) : "f"(x));
    return y;
}
__device__ __forceinline__ float sigm(float v) {
    return fmaf(tanh_fast(0.5f * v), 0.5f, 0.5f);
}

// One plane's dilated 3x3 contribution: 2 output channels x 4 gates x 8 px.
// Per ky: <=4 vector LDG + 6 LDS.128 feeding 192 FFMAs.
template <int DIL>
__device__ __forceinline__ void accum_plane(
    const float* __restrict__ plane,
    const float4* __restrict__ w0, const float4* __restrict__ w1,
    int row, int x0, float acc[2][4][8])
{
#pragma unroll
    for (int ky = 0; ky < 3; ky++) {
        const int yy = row + (ky - 1) * DIL;
        if (yy < 0 || yy >= HW) continue;
        const float* rp = plane + yy * HW;

        float vals[8 + 2 * DIL];
        {
            float4 m0 = __ldg((const float4*)(rp + x0));
            float4 m1 = __ldg((const float4*)(rp + x0 + 4));
            vals[DIL + 0] = m0.x; vals[DIL + 1] = m0.y;
            vals[DIL + 2] = m0.z; vals[DIL + 3] = m0.w;
            vals[DIL + 4] = m1.x; vals[DIL + 5] = m1.y;
            vals[DIL + 6] = m1.z; vals[DIL + 7] = m1.w;
        }
        if (DIL == 1) {
            vals[0] = (x0 > 0)      ? __ldg(rp + x0 - 1) : 0.f;
            vals[9] = (x0 + 8 < HW) ? __ldg(rp + x0 + 8) : 0.f;
        } else if (DIL == 2) {
            if (x0 > 0) {
                float2 l = __ldg((const float2*)(rp + x0 - 2));
                vals[0] = l.x; vals[1] = l.y;
            } else { vals[0] = 0.f; vals[1] = 0.f; }
            if (x0 + 8 < HW) {
                float2 r = __ldg((const float2*)(rp + x0 + 8));
                vals[10] = r.x; vals[11] = r.y;
            } else { vals[10] = 0.f; vals[11] = 0.f; }
        } else {  // DIL == 4
            if (x0 > 0) {
                float4 l = __ldg((const float4*)(rp + x0 - 4));
                vals[0] = l.x; vals[1] = l.y; vals[2] = l.z; vals[3] = l.w;
            } else { vals[0] = vals[1] = vals[2] = vals[3] = 0.f; }
            if (x0 + 8 < HW) {
                float4 r = __ldg((const float4*)(rp + x0 + 8));
                vals[12] = r.x; vals[13] = r.y; vals[14] = r.z; vals[15] = r.w;
            } else { vals[12] = vals[13] = vals[14] = vals[15] = 0.f; }
        }

#pragma unroll
        for (int kx = 0; kx < 3; kx++) {
            const float4 a4 = w0[ky * 3 + kx];   // LDS.128 broadcast, ch 0 gates
            const float4 b4 = w1[ky * 3 + kx];   // LDS.128 broadcast, ch 1 gates
#pragma unroll
            for (int px = 0; px < 8; px++) {
                const float v = vals[px + kx * DIL];
                acc[0][0][px] = fmaf(a4.x, v, acc[0][0][px]);
                acc[0][1][px] = fmaf(a4.y, v, acc[0][1][px]);
                acc[0][2][px] = fmaf(a4.z, v, acc[0][2][px]);
                acc[0][3][px] = fmaf(a4.w, v, acc[0][3][px]);
                acc[1][0][px] = fmaf(b4.x, v, acc[1][0][px]);
                acc[1][1][px] = fmaf(b4.y, v, acc[1][1][px]);
                acc[1][2][px] = fmaf(b4.z, v, acc[1][2][px]);
                acc[1][3][px] = fmaf(b4.w, v, acc[1][3][px]);
            }
        }
    }
}

// One fused step. Block: 128 threads = 16 rows x 64 cols; each thread:
// 2 output channels x 8 px. Block covers 2 hid channels.
template <int LAYER, int CIN_X, int DIL>
__global__ void __launch_bounds__(128) lstm_step(
    const float* __restrict__ x_in,
    const float* __restrict__ gw,     // [4*HID][CC][3][3]
    const float* __restrict__ gb,     // [4*HID]
    const float* __restrict__ rw,     // [HID][CIN_X] (layer 0) or null
    const float* __restrict__ rb,
    float* __restrict__ out_final,
    int t)
{
    constexpr int CC = CIN_X + HID;

    __shared__ float4 ws4[2][CC * 9];   // [ch][ci*9+k] -> 4 gates
    __shared__ float  rws[2][CIN_X];

    const int tid      = threadIdx.x;
    const int ytile    = blockIdx.x;          // 4 tiles of 16 rows
    const int co_group = blockIdx.y;          // 32 groups of 2 ch
    const int b        = blockIdx.z;
    const int row      = ytile * 16 + (tid >> 3);
    const int x0       = (tid & 7) << 3;      // 8 px per thread

    {
        float* wsf = (float*)ws4;
        for (int i = tid; i < 2 * CC * 9 * 4; i += 128) {
            int g  = i & 3;
            int r  = i >> 2;                 // cl*CC*9 + ci*9 + k
            int cl = r / (CC * 9);
            int ck = r - cl * CC * 9;
            wsf[i] = gw[(size_t)(g * HID + co_group * 2 + cl) * (CC * 9) + ck];
        }
    }
    if (LAYER == 0 && tid < 2 * CIN_X)
        rws[tid / CIN_X][tid % CIN_X] =
            rw[(co_group * 2 + tid / CIN_X) * CIN_X + (tid % CIN_X)];
    __syncthreads();

    const float* seq_in  = (LAYER == 0) ? x_in : ((LAYER == 1) ? g_buf0 : g_buf1);
    float*       seq_out = (LAYER == 0) ? g_buf0 : ((LAYER == 1) ? g_buf1 : out_final);

    const float* xt = seq_in + (size_t)(b * T + t) * CIN_X * PLANE;
    const float* hp = seq_out + (size_t)(b * T + (t - 1)) * HID * PLANE;  // valid t>0

    float acc[2][4][8] = {};

    {
        const float* plane = xt;
        const float4* w0 = ws4[0];
        const float4* w1 = ws4[1];
        for (int ci = 0; ci < CIN_X; ci++, plane += PLANE, w0 += 9, w1 += 9)
            accum_plane<DIL>(plane, w0, w1, row, x0, acc);
    }
    if (t > 0) {
        const float* plane = hp;
        const float4* w0 = ws4[0] + CIN_X * 9;
        const float4* w1 = ws4[1] + CIN_X * 9;
        for (int ci = 0; ci < HID; ci++, plane += PLANE, w0 += 9, w1 += 9)
            accum_plane<DIL>(plane, w0, w1, row, x0, acc);
    }

    // Residual (shared across the two channels only for layer>0 indexing; compute per ch)
    float res[2][8];
    if (LAYER == 0) {
#pragma unroll
        for (int cl = 0; cl < 2; cl++) {
            float rbv = __ldg(rb + co_group * 2 + cl);
#pragma unroll
            for (int px = 0; px < 8; px++) res[cl][px] = rbv;
        }
        const float* p = xt + row * HW + x0;
        for (int ci = 0; ci < CIN_X; ci++, p += PLANE) {
            float4 p0 = __ldg((const float4*)p);
            float4 p1 = __ldg((const float4*)(p + 4));
#pragma unroll
            for (int cl = 0; cl < 2; cl++) {
                float w = rws[cl][ci];
                res[cl][0] = fmaf(w, p0.x, res[cl][0]);
                res[cl][1] = fmaf(w, p0.y, res[cl][1]);
                res[cl][2] = fmaf(w, p0.z, res[cl][2]);
                res[cl][3] = fmaf(w, p0.w, res[cl][3]);
                res[cl][4] = fmaf(w, p1.x, res[cl][4]);
                res[cl][5] = fmaf(w, p1.y, res[cl][5]);
                res[cl][6] = fmaf(w, p1.z, res[cl][6]);
                res[cl][7] = fmaf(w, p1.w, res[cl][7]);
            }
        }
    } else {
#pragma unroll
        for (int cl = 0; cl < 2; cl++) {
            const float* p = xt + (size_t)(co_group * 2 + cl) * PLANE + row * HW + x0;
            float4 p0 = __ldg((const float4*)p);
            float4 p1 = __ldg((const float4*)(p + 4));
            res[cl][0] = p0.x; res[cl][1] = p0.y; res[cl][2] = p0.z; res[cl][3] = p0.w;
            res[cl][4] = p1.x; res[cl][5] = p1.y; res[cl][6] = p1.z; res[cl][7] = p1.w;
        }
    }

#pragma unroll
    for (int cl = 0; cl < 2; cl++) {
        const int co = co_group * 2 + cl;
        float gbv[4];
#pragma unroll
        for (int g = 0; g < 4; g++) gbv[g] = __ldg(gb + g * HID + co);

        float* cptr = g_c + (size_t)(b * HID + co) * PLANE + row * HW + x0;
        float* optr = seq_out + ((size_t)(b * T + t) * HID + co) * PLANE + row * HW + x0;

        float co_a[8];
        if (t > 0) {
            float4 c0 = *(const float4*)cptr;
            float4 c1 = *(const float4*)(cptr + 4);
            co_a[0] = c0.x; co_a[1] = c0.y; co_a[2] = c0.z; co_a[3] = c0.w;
            co_a[4] = c1.x; co_a[5] = c1.y; co_a[6] = c1.z; co_a[7] = c1.w;
        } else {
#pragma unroll
            for (int px = 0; px < 8; px++) co_a[px] = 0.f;
        }

        float cn_a[8], ho_a[8];
#pragma unroll
        for (int px = 0; px < 8; px++) {
            float iv = sigm(acc[cl][0][px] + gbv[0]);
            float fv = sigm(acc[cl][1][px] + gbv[1]);
            float gv = tanh_fast(acc[cl][2][px] + gbv[2]);
            float ov = sigm(acc[cl][3][px] + gbv[3]);
            float cn = fv * co_a[px] + iv * gv;
            cn_a[px] = cn;
            ho_a[px] = ov * tanh_fast(cn) + res[cl][px];
        }
        *(float4*)cptr       = make_float4(cn_a[0], cn_a[1], cn_a[2], cn_a[3]);
        *(float4*)(cptr + 4) = make_float4(cn_a[4], cn_a[5], cn_a[6], cn_a[7]);
        *(float4*)optr       = make_float4(ho_a[0], ho_a[1], ho_a[2], ho_a[3]);
        *(float4*)(optr + 4) = make_float4(ho_a[4], ho_a[5], ho_a[6], ho_a[7]);
    }
}

extern "C" void kernel_launch(void* const* d_in, const int* in_sizes, int n_in,
                              void* d_out, int out_size)
{
    (void)in_sizes; (void)n_in; (void)out_size;
    const float* x   = (const float*)d_in[0];
    const float* gw0 = (const float*)d_in[1];
    const float* gb0 = (const float*)d_in[2];
    const float* gw1 = (const float*)d_in[3];
    const float* gb1 = (const float*)d_in[4];
    const float* gw2 = (const float*)d_in[5];
    const float* gb2 = (const float*)d_in[6];
    const float* rw0 = (const float*)d_in[7];
    const float* rb0 = (const float*)d_in[8];
    float* out = (float*)d_out;

    dim3 grid(4, 32, B);   // 4 row-tiles x 32 ch-groups x batch
    for (int t = 0; t < T; t++)
        lstm_step<0, 32, 1><<<grid, 128>>>(x, gw0, gb0, rw0, rb0, out, t);
    for (int t = 0; t < T; t++)
        lstm_step<1, 64, 2><<<grid, 128>>>(x, gw1, gb1, nullptr, nullptr, out, t);
    for (int t = 0; t < T; t++)
        lstm_step<2, 64, 4><<<grid, 128>>>(x, gw2, gb2, nullptr, nullptr, out, t);
}

// round 8
// speedup vs baseline: 2.4378x; 1.0787x over previous
#include <cuda_runtime.h>
#include <math.h>

#define B     4
#define T     16
#define HID   64
#define HW    64
#define PLANE 4096   // 64*64

__device__ float g_buf0[(size_t)B * T * HID * PLANE];
__device__ float g_buf1[(size_t)B * T * HID * PLANE];
__device__ float g_c[(size_t)B * HID * PLANE];

typedef unsigned long long ull;

__device__ __forceinline__ float tanh_fast(float x) {
    float y;
    asm("tanh.approx.f32 %0, %1;" : "=f"(y) : "f"(x));
    return y;
}
__device__ __forceinline__ float sigm(float v) {
    return fmaf(tanh_fast(0.5f * v), 0.5f, 0.5f);
}
__device__ __forceinline__ ull splat2(float a) {
    ull r;
    asm("mov.b64 %0, {%1, %1};" : "=l"(r) : "f"(a));
    return r;
}
__device__ __forceinline__ void fma2(ull& d, ull a, ull b) {
    asm("fma.rn.f32x2 %0, %1, %2, %0;" : "+l"(d) : "l"(a), "l"(b));
}
__device__ __forceinline__ void unpack2(ull v, float& lo, float& hi) {
    asm("mov.b64 {%0, %1}, %2;" : "=f"(lo), "=f"(hi) : "l"(v));
}

// One plane's dilated 3x3 contribution. Packed-gate layout:
// acc[ch][pair][px], pair 0 lanes = (i,f), pair 1 lanes = (g,o).
// Per (ci,ky): <=4 LDG + ~(8+2D) splats + 6 LDS.128, feeding 96 FFMA2.
template <int DIL>
__device__ __forceinline__ void accum_plane(
    const float* __restrict__ plane,
    const ulonglong2* __restrict__ w0, const ulonglong2* __restrict__ w1,
    int row, int x0, ull acc[2][2][8])
{
#pragma unroll
    for (int ky = 0; ky < 3; ky++) {
        const int yy = row + (ky - 1) * DIL;
        if (yy < 0 || yy >= HW) continue;
        const float* rp = plane + yy * HW;

        float vals[8 + 2 * DIL];
        {
            float4 m0 = __ldg((const float4*)(rp + x0));
            float4 m1 = __ldg((const float4*)(rp + x0 + 4));
            vals[DIL + 0] = m0.x; vals[DIL + 1] = m0.y;
            vals[DIL + 2] = m0.z; vals[DIL + 3] = m0.w;
            vals[DIL + 4] = m1.x; vals[DIL + 5] = m1.y;
            vals[DIL + 6] = m1.z; vals[DIL + 7] = m1.w;
        }
        if (DIL == 1) {
            vals[0] = (x0 > 0)      ? __ldg(rp + x0 - 1) : 0.f;
            vals[9] = (x0 + 8 < HW) ? __ldg(rp + x0 + 8) : 0.f;
        } else if (DIL == 2) {
            if (x0 > 0) {
                float2 l = __ldg((const float2*)(rp + x0 - 2));
                vals[0] = l.x; vals[1] = l.y;
            } else { vals[0] = 0.f; vals[1] = 0.f; }
            if (x0 + 8 < HW) {
                float2 r = __ldg((const float2*)(rp + x0 + 8));
                vals[10] = r.x; vals[11] = r.y;
            } else { vals[10] = 0.f; vals[11] = 0.f; }
        } else {  // DIL == 4
            if (x0 > 0) {
                float4 l = __ldg((const float4*)(rp + x0 - 4));
                vals[0] = l.x; vals[1] = l.y; vals[2] = l.z; vals[3] = l.w;
            } else { vals[0] = vals[1] = vals[2] = vals[3] = 0.f; }
            if (x0 + 8 < HW) {
                float4 r = __ldg((const float4*)(rp + x0 + 8));
                vals[12] = r.x; vals[13] = r.y; vals[14] = r.z; vals[15] = r.w;
            } else { vals[12] = vals[13] = vals[14] = vals[15] = 0.f; }
        }

        // Splat each value once; reused across 3 kx, 2 ch, 2 gate-pairs.
        ull vp[8 + 2 * DIL];
#pragma unroll
        for (int j = 0; j < 8 + 2 * DIL; j++) vp[j] = splat2(vals[j]);

#pragma unroll
        for (int kx = 0; kx < 3; kx++) {
            const ulonglong2 wa = w0[ky * 3 + kx];  // lanes: (wi,wf),(wg,wo) ch0
            const ulonglong2 wb = w1[ky * 3 + kx];  // ch1
#pragma unroll
            for (int px = 0; px < 8; px++) {
                const ull v = vp[px + kx * DIL];
                fma2(acc[0][0][px], wa.x, v);
                fma2(acc[0][1][px], wa.y, v);
                fma2(acc[1][0][px], wb.x, v);
                fma2(acc[1][1][px], wb.y, v);
            }
        }
    }
}

// One fused step. Block: 128 threads = 16 rows x 64 cols; each thread:
// 2 output channels x 8 px, gates packed 2-wide in f32x2 lanes.
template <int LAYER, int CIN_X, int DIL>
__global__ void __launch_bounds__(128) lstm_step(
    const float* __restrict__ x_in,
    const float* __restrict__ gw,     // [4*HID][CC][3][3]
    const float* __restrict__ gb,     // [4*HID]
    const float* __restrict__ rw,     // [HID][CIN_X] (layer 0) or null
    const float* __restrict__ rb,
    float* __restrict__ out_final,
    int t)
{
    constexpr int CC = CIN_X + HID;

    __shared__ float4 ws4[2][CC * 9];   // [ch][ci*9+k] -> (wi,wf,wg,wo)
    __shared__ float  rws[2][CIN_X];

    const int tid      = threadIdx.x;
    const int ytile    = blockIdx.x;          // 4 tiles of 16 rows
    const int co_group = blockIdx.y;          // 32 groups of 2 ch
    const int b        = blockIdx.z;
    const int row      = ytile * 16 + (tid >> 3);
    const int x0       = (tid & 7) << 3;      // 8 px per thread

    {
        float* wsf = (float*)ws4;
        for (int i = tid; i < 2 * CC * 9 * 4; i += 128) {
            int g  = i & 3;
            int r  = i >> 2;                 // cl*CC*9 + ci*9 + k
            int cl = r / (CC * 9);
            int ck = r - cl * CC * 9;
            wsf[i] = gw[(size_t)(g * HID + co_group * 2 + cl) * (CC * 9) + ck];
        }
    }
    if (LAYER == 0 && tid < 2 * CIN_X)
        rws[tid / CIN_X][tid % CIN_X] =
            rw[(co_group * 2 + tid / CIN_X) * CIN_X + (tid % CIN_X)];
    __syncthreads();

    const float* seq_in  = (LAYER == 0) ? x_in : ((LAYER == 1) ? g_buf0 : g_buf1);
    float*       seq_out = (LAYER == 0) ? g_buf0 : ((LAYER == 1) ? g_buf1 : out_final);

    const float* xt = seq_in + (size_t)(b * T + t) * CIN_X * PLANE;
    const float* hp = seq_out + (size_t)(b * T + (t - 1)) * HID * PLANE;  // valid t>0

    ull acc[2][2][8];
#pragma unroll
    for (int cl = 0; cl < 2; cl++)
#pragma unroll
        for (int gp = 0; gp < 2; gp++)
#pragma unroll
            for (int px = 0; px < 8; px++) acc[cl][gp][px] = 0ULL;

    {
        const float* plane = xt;
        const ulonglong2* w0 = (const ulonglong2*)ws4[0];
        const ulonglong2* w1 = (const ulonglong2*)ws4[1];
        for (int ci = 0; ci < CIN_X; ci++, plane += PLANE, w0 += 9, w1 += 9)
            accum_plane<DIL>(plane, w0, w1, row, x0, acc);
    }
    if (t > 0) {
        const float* plane = hp;
        const ulonglong2* w0 = (const ulonglong2*)ws4[0] + CIN_X * 9;
        const ulonglong2* w1 = (const ulonglong2*)ws4[1] + CIN_X * 9;
        for (int ci = 0; ci < HID; ci++, plane += PLANE, w0 += 9, w1 += 9)
            accum_plane<DIL>(plane, w0, w1, row, x0, acc);
    }

    // Residual
    float res[2][8];
    if (LAYER == 0) {
#pragma unroll
        for (int cl = 0; cl < 2; cl++) {
            float rbv = __ldg(rb + co_group * 2 + cl);
#pragma unroll
            for (int px = 0; px < 8; px++) res[cl][px] = rbv;
        }
        const float* p = xt + row * HW + x0;
        for (int ci = 0; ci < CIN_X; ci++, p += PLANE) {
            float4 p0 = __ldg((const float4*)p);
            float4 p1 = __ldg((const float4*)(p + 4));
#pragma unroll
            for (int cl = 0; cl < 2; cl++) {
                float w = rws[cl][ci];
                res[cl][0] = fmaf(w, p0.x, res[cl][0]);
                res[cl][1] = fmaf(w, p0.y, res[cl][1]);
                res[cl][2] = fmaf(w, p0.z, res[cl][2]);
                res[cl][3] = fmaf(w, p0.w, res[cl][3]);
                res[cl][4] = fmaf(w, p1.x, res[cl][4]);
                res[cl][5] = fmaf(w, p1.y, res[cl][5]);
                res[cl][6] = fmaf(w, p1.z, res[cl][6]);
                res[cl][7] = fmaf(w, p1.w, res[cl][7]);
            }
        }
    } else {
#pragma unroll
        for (int cl = 0; cl < 2; cl++) {
            const float* p = xt + (size_t)(co_group * 2 + cl) * PLANE + row * HW + x0;
            float4 p0 = __ldg((const float4*)p);
            float4 p1 = __ldg((const float4*)(p + 4));
            res[cl][0] = p0.x; res[cl][1] = p0.y; res[cl][2] = p0.z; res[cl][3] = p0.w;
            res[cl][4] = p1.x; res[cl][5] = p1.y; res[cl][6] = p1.z; res[cl][7] = p1.w;
        }
    }

#pragma unroll
    for (int cl = 0; cl < 2; cl++) {
        const int co = co_group * 2 + cl;
        float gbv[4];
#pragma unroll
        for (int g = 0; g < 4; g++) gbv[g] = __ldg(gb + g * HID + co);

        float* cptr = g_c + (size_t)(b * HID + co) * PLANE + row * HW + x0;
        float* optr = seq_out + ((size_t)(b * T + t) * HID + co) * PLANE + row * HW + x0;

        float co_a[8];
        if (t > 0) {
            float4 c0 = *(const float4*)cptr;
            float4 c1 = *(const float4*)(cptr + 4);
            co_a[0] = c0.x; co_a[1] = c0.y; co_a[2] = c0.z; co_a[3] = c0.w;
            co_a[4] = c1.x; co_a[5] = c1.y; co_a[6] = c1.z; co_a[7] = c1.w;
        } else {
#pragma unroll
            for (int px = 0; px < 8; px++) co_a[px] = 0.f;
        }

        float cn_a[8], ho_a[8];
#pragma unroll
        for (int px = 0; px < 8; px++) {
            float aI, aF, aG, aO;
            unpack2(acc[cl][0][px], aI, aF);
            unpack2(acc[cl][1][px], aG, aO);
            float iv = sigm(aI + gbv[0]);
            float fv = sigm(aF + gbv[1]);
            float gv = tanh_fast(aG + gbv[2]);
            float ov = sigm(aO + gbv[3]);
            float cn = fv * co_a[px] + iv * gv;
            cn_a[px] = cn;
            ho_a[px] = ov * tanh_fast(cn) + res[cl][px];
        }
        *(float4*)cptr       = make_float4(cn_a[0], cn_a[1], cn_a[2], cn_a[3]);
        *(float4*)(cptr + 4) = make_float4(cn_a[4], cn_a[5], cn_a[6], cn_a[7]);
        *(float4*)optr       = make_float4(ho_a[0], ho_a[1], ho_a[2], ho_a[3]);
        *(float4*)(optr + 4) = make_float4(ho_a[4], ho_a[5], ho_a[6], ho_a[7]);
    }
}

extern "C" void kernel_launch(void* const* d_in, const int* in_sizes, int n_in,
                              void* d_out, int out_size)
{
    (void)in_sizes; (void)n_in; (void)out_size;
    const float* x   = (const float*)d_in[0];
    const float* gw0 = (const float*)d_in[1];
    const float* gb0 = (const float*)d_in[2];
    const float* gw1 = (const float*)d_in[3];
    const float* gb1 = (const float*)d_in[4];
    const float* gw2 = (const float*)d_in[5];
    const float* gb2 = (const float*)d_in[6];
    const float* rw0 = (const float*)d_in[7];
    const float* rb0 = (const float*)d_in[8];
    float* out = (float*)d_out;

    dim3 grid(4, 32, B);   // 4 row-tiles x 32 ch-groups x batch
    for (int t = 0; t < T; t++)
        lstm_step<0, 32, 1><<<grid, 128>>>(x, gw0, gb0, rw0, rb0, out, t);
    for (int t = 0; t < T; t++)
        lstm_step<1, 64, 2><<<grid, 128>>>(x, gw1, gb1, nullptr, nullptr, out, t);
    for (int t = 0; t < T; t++)
        lstm_step<2, 64, 4><<<grid, 128>>>(x, gw2, gb2, nullptr, nullptr, out, t);
}

// round 9
// speedup vs baseline: 3.2977x; 1.3527x over previous
#include <cuda_runtime.h>
#include <math.h>

#define B     4
#define T     16
#define HID   64
#define HW    64
#define PLANE 4096   // 64*64

__device__ float g_buf0[(size_t)B * T * HID * PLANE];
__device__ float g_buf1[(size_t)B * T * HID * PLANE];
__device__ float g_c[3][(size_t)B * HID * PLANE];   // per-layer: layers run concurrently

typedef unsigned long long ull;

__device__ __forceinline__ float tanh_fast(float x) {
    float y;
    asm("tanh.approx.f32 %0, %1;" : "=f"(y) : "f"(x));
    return y;
}
__device__ __forceinline__ float sigm(float v) {
    return fmaf(tanh_fast(0.5f * v), 0.5f, 0.5f);
}
__device__ __forceinline__ ull splat2(float a) {
    ull r;
    asm("mov.b64 %0, {%1, %1};" : "=l"(r) : "f"(a));
    return r;
}
__device__ __forceinline__ void fma2(ull& d, ull a, ull b) {
    asm("fma.rn.f32x2 %0, %1, %2, %0;" : "+l"(d) : "l"(a), "l"(b));
}
__device__ __forceinline__ void unpack2(ull v, float& lo, float& hi) {
    asm("mov.b64 {%0, %1}, %2;" : "=f"(lo), "=f"(hi) : "l"(v));
}

// One plane's dilated 3x3 contribution. acc[ch][pair][px]; pair lanes = (i,f),(g,o).
template <int DIL>
__device__ __forceinline__ void accum_plane(
    const float* __restrict__ plane,
    const ulonglong2* __restrict__ w0, const ulonglong2* __restrict__ w1,
    int row, int x0, ull acc[2][2][8])
{
#pragma unroll
    for (int ky = 0; ky < 3; ky++) {
        const int yy = row + (ky - 1) * DIL;
        if (yy < 0 || yy >= HW) continue;
        const float* rp = plane + yy * HW;

        float vals[8 + 2 * DIL];
        {
            float4 m0 = __ldg((const float4*)(rp + x0));
            float4 m1 = __ldg((const float4*)(rp + x0 + 4));
            vals[DIL + 0] = m0.x; vals[DIL + 1] = m0.y;
            vals[DIL + 2] = m0.z; vals[DIL + 3] = m0.w;
            vals[DIL + 4] = m1.x; vals[DIL + 5] = m1.y;
            vals[DIL + 6] = m1.z; vals[DIL + 7] = m1.w;
        }
        if (DIL == 1) {
            vals[0] = (x0 > 0)      ? __ldg(rp + x0 - 1) : 0.f;
            vals[9] = (x0 + 8 < HW) ? __ldg(rp + x0 + 8) : 0.f;
        } else if (DIL == 2) {
            if (x0 > 0) {
                float2 l = __ldg((const float2*)(rp + x0 - 2));
                vals[0] = l.x; vals[1] = l.y;
            } else { vals[0] = 0.f; vals[1] = 0.f; }
            if (x0 + 8 < HW) {
                float2 r = __ldg((const float2*)(rp + x0 + 8));
                vals[10] = r.x; vals[11] = r.y;
            } else { vals[10] = 0.f; vals[11] = 0.f; }
        } else {  // DIL == 4
            if (x0 > 0) {
                float4 l = __ldg((const float4*)(rp + x0 - 4));
                vals[0] = l.x; vals[1] = l.y; vals[2] = l.z; vals[3] = l.w;
            } else { vals[0] = vals[1] = vals[2] = vals[3] = 0.f; }
            if (x0 + 8 < HW) {
                float4 r = __ldg((const float4*)(rp + x0 + 8));
                vals[12] = r.x; vals[13] = r.y; vals[14] = r.z; vals[15] = r.w;
            } else { vals[12] = vals[13] = vals[14] = vals[15] = 0.f; }
        }

        ull vp[8 + 2 * DIL];
#pragma unroll
        for (int j = 0; j < 8 + 2 * DIL; j++) vp[j] = splat2(vals[j]);

#pragma unroll
        for (int kx = 0; kx < 3; kx++) {
            const ulonglong2 wa = w0[ky * 3 + kx];
            const ulonglong2 wb = w1[ky * 3 + kx];
#pragma unroll
            for (int px = 0; px < 8; px++) {
                const ull v = vp[px + kx * DIL];
                fma2(acc[0][0][px], wa.x, v);
                fma2(acc[0][1][px], wa.y, v);
                fma2(acc[1][0][px], wb.x, v);
                fma2(acc[1][1][px], wb.y, v);
            }
        }
    }
}

template <int LAYER, int CIN_X, int DIL>
__global__ void __launch_bounds__(128) lstm_step(
    const float* __restrict__ x_in,
    const float* __restrict__ gw,
    const float* __restrict__ gb,
    const float* __restrict__ rw,
    const float* __restrict__ rb,
    float* __restrict__ out_final,
    int t)
{
    constexpr int CC = CIN_X + HID;

    __shared__ float4 ws4[2][CC * 9];
    __shared__ float  rws[2][CIN_X];

    const int tid      = threadIdx.x;
    const int ytile    = blockIdx.x;
    const int co_group = blockIdx.y;
    const int b        = blockIdx.z;
    const int row      = ytile * 16 + (tid >> 3);
    const int x0       = (tid & 7) << 3;

    {
        float* wsf = (float*)ws4;
        for (int i = tid; i < 2 * CC * 9 * 4; i += 128) {
            int g  = i & 3;
            int r  = i >> 2;
            int cl = r / (CC * 9);
            int ck = r - cl * CC * 9;
            wsf[i] = gw[(size_t)(g * HID + co_group * 2 + cl) * (CC * 9) + ck];
        }
    }
    if (LAYER == 0 && tid < 2 * CIN_X)
        rws[tid / CIN_X][tid % CIN_X] =
            rw[(co_group * 2 + tid / CIN_X) * CIN_X + (tid % CIN_X)];
    __syncthreads();

    const float* seq_in  = (LAYER == 0) ? x_in : ((LAYER == 1) ? g_buf0 : g_buf1);
    float*       seq_out = (LAYER == 0) ? g_buf0 : ((LAYER == 1) ? g_buf1 : out_final);

    const float* xt = seq_in + (size_t)(b * T + t) * CIN_X * PLANE;
    const float* hp = seq_out + (size_t)(b * T + (t - 1)) * HID * PLANE;

    ull acc[2][2][8];
#pragma unroll
    for (int cl = 0; cl < 2; cl++)
#pragma unroll
        for (int gp = 0; gp < 2; gp++)
#pragma unroll
            for (int px = 0; px < 8; px++) acc[cl][gp][px] = 0ULL;

    {
        const float* plane = xt;
        const ulonglong2* w0 = (const ulonglong2*)ws4[0];
        const ulonglong2* w1 = (const ulonglong2*)ws4[1];
        for (int ci = 0; ci < CIN_X; ci++, plane += PLANE, w0 += 9, w1 += 9)
            accum_plane<DIL>(plane, w0, w1, row, x0, acc);
    }
    if (t > 0) {
        const float* plane = hp;
        const ulonglong2* w0 = (const ulonglong2*)ws4[0] + CIN_X * 9;
        const ulonglong2* w1 = (const ulonglong2*)ws4[1] + CIN_X * 9;
        for (int ci = 0; ci < HID; ci++, plane += PLANE, w0 += 9, w1 += 9)
            accum_plane<DIL>(plane, w0, w1, row, x0, acc);
    }

    float res[2][8];
    if (LAYER == 0) {
#pragma unroll
        for (int cl = 0; cl < 2; cl++) {
            float rbv = __ldg(rb + co_group * 2 + cl);
#pragma unroll
            for (int px = 0; px < 8; px++) res[cl][px] = rbv;
        }
        const float* p = xt + row * HW + x0;
        for (int ci = 0; ci < CIN_X; ci++, p += PLANE) {
            float4 p0 = __ldg((const float4*)p);
            float4 p1 = __ldg((const float4*)(p + 4));
#pragma unroll
            for (int cl = 0; cl < 2; cl++) {
                float w = rws[cl][ci];
                res[cl][0] = fmaf(w, p0.x, res[cl][0]);
                res[cl][1] = fmaf(w, p0.y, res[cl][1]);
                res[cl][2] = fmaf(w, p0.z, res[cl][2]);
                res[cl][3] = fmaf(w, p0.w, res[cl][3]);
                res[cl][4] = fmaf(w, p1.x, res[cl][4]);
                res[cl][5] = fmaf(w, p1.y, res[cl][5]);
                res[cl][6] = fmaf(w, p1.z, res[cl][6]);
                res[cl][7] = fmaf(w, p1.w, res[cl][7]);
            }
        }
    } else {
#pragma unroll
        for (int cl = 0; cl < 2; cl++) {
            const float* p = xt + (size_t)(co_group * 2 + cl) * PLANE + row * HW + x0;
            float4 p0 = __ldg((const float4*)p);
            float4 p1 = __ldg((const float4*)(p + 4));
            res[cl][0] = p0.x; res[cl][1] = p0.y; res[cl][2] = p0.z; res[cl][3] = p0.w;
            res[cl][4] = p1.x; res[cl][5] = p1.y; res[cl][6] = p1.z; res[cl][7] = p1.w;
        }
    }

#pragma unroll
    for (int cl = 0; cl < 2; cl++) {
        const int co = co_group * 2 + cl;
        float gbv[4];
#pragma unroll
        for (int g = 0; g < 4; g++) gbv[g] = __ldg(gb + g * HID + co);

        float* cptr = g_c[LAYER] + (size_t)(b * HID + co) * PLANE + row * HW + x0;
        float* optr = seq_out + ((size_t)(b * T + t) * HID + co) * PLANE + row * HW + x0;

        float co_a[8];
        if (t > 0) {
            float4 c0 = *(const float4*)cptr;
            float4 c1 = *(const float4*)(cptr + 4);
            co_a[0] = c0.x; co_a[1] = c0.y; co_a[2] = c0.z; co_a[3] = c0.w;
            co_a[4] = c1.x; co_a[5] = c1.y; co_a[6] = c1.z; co_a[7] = c1.w;
        } else {
#pragma unroll
            for (int px = 0; px < 8; px++) co_a[px] = 0.f;
        }

        float cn_a[8], ho_a[8];
#pragma unroll
        for (int px = 0; px < 8; px++) {
            float aI, aF, aG, aO;
            unpack2(acc[cl][0][px], aI, aF);
            unpack2(acc[cl][1][px], aG, aO);
            float iv = sigm(aI + gbv[0]);
            float fv = sigm(aF + gbv[1]);
            float gv = tanh_fast(aG + gbv[2]);
            float ov = sigm(aO + gbv[3]);
            float cn = fv * co_a[px] + iv * gv;
            cn_a[px] = cn;
            ho_a[px] = ov * tanh_fast(cn) + res[cl][px];
        }
        *(float4*)cptr       = make_float4(cn_a[0], cn_a[1], cn_a[2], cn_a[3]);
        *(float4*)(cptr + 4) = make_float4(cn_a[4], cn_a[5], cn_a[6], cn_a[7]);
        *(float4*)optr       = make_float4(ho_a[0], ho_a[1], ho_a[2], ho_a[3]);
        *(float4*)(optr + 4) = make_float4(ho_a[4], ho_a[5], ho_a[6], ho_a[7]);
    }
}

// Layer-pipelined launch: L1(t) waits on L0(t) via event; L2(t) on L1(t).
// Fork-join event pattern is graph-capture legal; all forks join stream 0 at end.
extern "C" void kernel_launch(void* const* d_in, const int* in_sizes, int n_in,
                              void* d_out, int out_size)
{
    (void)in_sizes; (void)n_in; (void)out_size;
    const float* x   = (const float*)d_in[0];
    const float* gw0 = (const float*)d_in[1];
    const float* gb0 = (const float*)d_in[2];
    const float* gw1 = (const float*)d_in[3];
    const float* gb1 = (const float*)d_in[4];
    const float* gw2 = (const float*)d_in[5];
    const float* gb2 = (const float*)d_in[6];
    const float* rw0 = (const float*)d_in[7];
    const float* rb0 = (const float*)d_in[8];
    float* out = (float*)d_out;

    // Host-side stream/event objects, created once (no device memory involved;
    // identical launched work on every call).
    static cudaStream_t s1 = nullptr, s2 = nullptr;
    static cudaEvent_t  e0[T], e1[T], f1, f2;
    if (s1 == nullptr) {
        cudaStreamCreateWithFlags(&s1, cudaStreamNonBlocking);
        cudaStreamCreateWithFlags(&s2, cudaStreamNonBlocking);
        for (int t = 0; t < T; t++) {
            cudaEventCreateWithFlags(&e0[t], cudaEventDisableTiming);
            cudaEventCreateWithFlags(&e1[t], cudaEventDisableTiming);
        }
        cudaEventCreateWithFlags(&f1, cudaEventDisableTiming);
        cudaEventCreateWithFlags(&f2, cudaEventDisableTiming);
    }

    dim3 grid(4, 32, B);
    for (int t = 0; t < T; t++) {
        lstm_step<0, 32, 1><<<grid, 128, 0, 0>>>(x, gw0, gb0, rw0, rb0, out, t);
        cudaEventRecord(e0[t], 0);
        cudaStreamWaitEvent(s1, e0[t], 0);
        lstm_step<1, 64, 2><<<grid, 128, 0, s1>>>(x, gw1, gb1, nullptr, nullptr, out, t);
        cudaEventRecord(e1[t], s1);
        cudaStreamWaitEvent(s2, e1[t], 0);
        lstm_step<2, 64, 4><<<grid, 128, 0, s2>>>(x, gw2, gb2, nullptr, nullptr, out, t);
    }
    cudaEventRecord(f1, s1);
    cudaEventRecord(f2, s2);
    cudaStreamWaitEvent(0, f1, 0);
    cudaStreamWaitEvent(0, f2, 0);
}